// round 4
// baseline (speedup 1.0000x reference)
#include <cuda_runtime.h>

#define NCLASS 128
#define NBLK   608          // 152 SMs x 4 resident blocks -> single wave
#define NTHR   256
#define UNROLL 8

// Global scratch — zero-initialized at module load; the finishing block
// re-zeros after consuming so every graph replay starts from a clean state.
__device__ float        g_colsum[NCLASS];
__device__ unsigned int g_counts[NCLASS];
__device__ float        g_picked;
__device__ unsigned int g_done;

// One warp per row. Lane l owns columns [4l, 4l+3] via one float4 load.
// 8-row unroll => 8 LDG.128 in flight per thread. The last block to finish
// performs the finalize inline (no second kernel launch).
__global__ __launch_bounds__(NTHR, 4) void loss_main_kernel(
    const float* __restrict__ pred,
    const int*   __restrict__ tgt,
    float*       __restrict__ out,
    int n)
{
    __shared__ float        s_colsum[NCLASS];
    __shared__ unsigned int s_counts[NCLASS];
    __shared__ float        s_picked;
    __shared__ unsigned int s_last;

    const int tid  = threadIdx.x;
    const int lane = tid & 31;
    const int wrp  = tid >> 5;

    if (tid < NCLASS) { s_colsum[tid] = 0.0f; s_counts[tid] = 0u; }
    if (tid == 0) s_picked = 0.0f;
    __syncthreads();

    const int gwarp = blockIdx.x * (NTHR >> 5) + wrp;
    const int W     = NBLK * (NTHR >> 5);     // total warps (stride)

    float a0 = 0.f, a1 = 0.f, a2 = 0.f, a3 = 0.f;
    float pick = 0.f;

    int r = gwarp;
    for (; r + (UNROLL - 1) * W < n; r += UNROLL * W) {
        float4 v[UNROLL];
        int    t[UNROLL];
        #pragma unroll
        for (int j = 0; j < UNROLL; j++) {
            const int rj = r + j * W;
            v[j] = __ldcs(reinterpret_cast<const float4*>(
                       pred + (size_t)rj * NCLASS + lane * 4));
            t[j] = tgt[rj];
        }
        #pragma unroll
        for (int j = 0; j < UNROLL; j++) {
            a0 += __expf(v[j].x); a1 += __expf(v[j].y);
            a2 += __expf(v[j].z); a3 += __expf(v[j].w);
            if ((t[j] >> 2) == lane) {
                const int k = t[j] & 3;
                pick += (k == 0) ? v[j].x : (k == 1) ? v[j].y
                      : (k == 2) ? v[j].z : v[j].w;
            }
            if (lane == j) atomicAdd(&s_counts[t[j]], 1u);  // lane j handles row j
        }
    }
    // Tail
    for (; r < n; r += W) {
        const float4 v = __ldcs(reinterpret_cast<const float4*>(
                             pred + (size_t)r * NCLASS + lane * 4));
        const int t = tgt[r];
        a0 += __expf(v.x); a1 += __expf(v.y); a2 += __expf(v.z); a3 += __expf(v.w);
        if ((t >> 2) == lane) {
            const int k = t & 3;
            pick += (k == 0) ? v.x : (k == 1) ? v.y : (k == 2) ? v.z : v.w;
        }
        if (lane == 0) atomicAdd(&s_counts[t], 1u);
    }

    // Warp-reduce picked sum.
    #pragma unroll
    for (int off = 16; off > 0; off >>= 1)
        pick += __shfl_xor_sync(0xFFFFFFFFu, pick, off);
    if (lane == 0) atomicAdd(&s_picked, pick);

    // Per-lane column partials -> shared (cross-warp combine).
    atomicAdd(&s_colsum[lane * 4 + 0], a0);
    atomicAdd(&s_colsum[lane * 4 + 1], a1);
    atomicAdd(&s_colsum[lane * 4 + 2], a2);
    atomicAdd(&s_colsum[lane * 4 + 3], a3);
    __syncthreads();

    // Flush block partials to global.
    if (tid < NCLASS) {
        atomicAdd(&g_colsum[tid], s_colsum[tid]);
        if (s_counts[tid]) atomicAdd(&g_counts[tid], s_counts[tid]);
    }
    if (tid == 0) atomicAdd(&g_picked, s_picked);

    // ---- inline finalize: last block to flush does the reduction ----
    __threadfence();
    if (tid == 0)
        s_last = (atomicAdd(&g_done, 1u) == NBLK - 1u);
    __syncthreads();
    if (!s_last) return;

    // This block runs after all blocks' atomics are globally visible.
    if (tid < NCLASS) {
        float diff = fabsf((float)g_counts[tid] - g_colsum[tid]);
        const float picked = g_picked;

        // Re-zero scratch for the next graph replay (after reads above).
        g_colsum[tid] = 0.0f;
        g_counts[tid] = 0u;
        if (tid == 0) { g_picked = 0.0f; g_done = 0u; }

        #pragma unroll
        for (int off = 16; off > 0; off >>= 1)
            diff += __shfl_xor_sync(0xFFFFFFFFu, diff, off);
        if (lane == 0) s_colsum[wrp] = diff;   // reuse smem for 4 partials
        __syncwarp();
        // warp 0 waits for warps 1-3 partials via a block sync below
    }
    __syncthreads();
    if (tid == 0) {
        const float extra = (s_colsum[0] + s_colsum[1] + s_colsum[2] + s_colsum[3])
                            / (float)n;
        out[0] = -g_picked /* already zeroed */ * 0.0f  // (placeholder avoided below)
               ;
    }
    // NOTE: g_picked was zeroed above; use the value captured per-thread.
    // Recompute correctly: thread 0 of warp 0 holds nothing — do it via smem.
}

// --- The finalize above must not read zeroed g_picked; keep it simple and
// --- correct: a dedicated tiny path using a captured shared copy.
__global__ void unused_kernel() {}

extern "C" void kernel_launch(void* const* d_in, const int* in_sizes, int n_in,
                              void* d_out, int out_size);

// ---------------------------------------------------------------------------
// The above finalize sketch had an ordering hazard (zeroing g_picked before
// the final write). Clean implementation below replaces it: capture all
// scratch into shared/registers FIRST, then zero, then compute.
// ---------------------------------------------------------------------------

__global__ __launch_bounds__(NTHR, 4) void loss_fused_kernel(
    const float* __restrict__ pred,
    const int*   __restrict__ tgt,
    float*       __restrict__ out,
    int n)
{
    __shared__ float        s_colsum[NCLASS];
    __shared__ unsigned int s_counts[NCLASS];
    __shared__ float        s_picked;
    __shared__ unsigned int s_last;
    __shared__ float        s_fin[5];   // 4 warp partials + picked copy

    const int tid  = threadIdx.x;
    const int lane = tid & 31;
    const int wrp  = tid >> 5;

    if (tid < NCLASS) { s_colsum[tid] = 0.0f; s_counts[tid] = 0u; }
    if (tid == 0) s_picked = 0.0f;
    __syncthreads();

    const int gwarp = blockIdx.x * (NTHR >> 5) + wrp;
    const int W     = NBLK * (NTHR >> 5);

    float a0 = 0.f, a1 = 0.f, a2 = 0.f, a3 = 0.f;
    float pick = 0.f;

    int r = gwarp;
    for (; r + (UNROLL - 1) * W < n; r += UNROLL * W) {
        float4 v[UNROLL];
        int    t[UNROLL];
        #pragma unroll
        for (int j = 0; j < UNROLL; j++) {
            const int rj = r + j * W;
            v[j] = __ldcs(reinterpret_cast<const float4*>(
                       pred + (size_t)rj * NCLASS + lane * 4));
            t[j] = tgt[rj];
        }
        #pragma unroll
        for (int j = 0; j < UNROLL; j++) {
            a0 += __expf(v[j].x); a1 += __expf(v[j].y);
            a2 += __expf(v[j].z); a3 += __expf(v[j].w);
            if ((t[j] >> 2) == lane) {
                const int k = t[j] & 3;
                pick += (k == 0) ? v[j].x : (k == 1) ? v[j].y
                      : (k == 2) ? v[j].z : v[j].w;
            }
            if (lane == j) atomicAdd(&s_counts[t[j]], 1u);
        }
    }
    for (; r < n; r += W) {
        const float4 v = __ldcs(reinterpret_cast<const float4*>(
                             pred + (size_t)r * NCLASS + lane * 4));
        const int t = tgt[r];
        a0 += __expf(v.x); a1 += __expf(v.y); a2 += __expf(v.z); a3 += __expf(v.w);
        if ((t >> 2) == lane) {
            const int k = t & 3;
            pick += (k == 0) ? v.x : (k == 1) ? v.y : (k == 2) ? v.z : v.w;
        }
        if (lane == 0) atomicAdd(&s_counts[t], 1u);
    }

    #pragma unroll
    for (int off = 16; off > 0; off >>= 1)
        pick += __shfl_xor_sync(0xFFFFFFFFu, pick, off);
    if (lane == 0) atomicAdd(&s_picked, pick);

    atomicAdd(&s_colsum[lane * 4 + 0], a0);
    atomicAdd(&s_colsum[lane * 4 + 1], a1);
    atomicAdd(&s_colsum[lane * 4 + 2], a2);
    atomicAdd(&s_colsum[lane * 4 + 3], a3);
    __syncthreads();

    if (tid < NCLASS) {
        atomicAdd(&g_colsum[tid], s_colsum[tid]);
        if (s_counts[tid]) atomicAdd(&g_counts[tid], s_counts[tid]);
    }
    if (tid == 0) atomicAdd(&g_picked, s_picked);

    // ---- inline finalize by the last block to flush ----
    __threadfence();
    if (tid == 0)
        s_last = (atomicAdd(&g_done, 1u) == (unsigned)(NBLK - 1)) ? 1u : 0u;
    __syncthreads();
    if (!s_last) return;

    // All blocks' global atomics are visible (fence before counter + atomic
    // acquire semantics of reaching NBLK-1 observations).
    float diff   = 0.0f;
    float picked = 0.0f;
    if (tid < NCLASS) {
        diff = fabsf((float)g_counts[tid] - g_colsum[tid]);
        // capture picked once
        if (tid == 0) picked = g_picked;
        // re-zero scratch for next replay (reads complete for this thread)
        g_colsum[tid] = 0.0f;
        g_counts[tid] = 0u;
    }
    if (tid == 0) { s_fin[4] = picked; g_picked = 0.0f; g_done = 0u; }

    #pragma unroll
    for (int off = 16; off > 0; off >>= 1)
        diff += __shfl_xor_sync(0xFFFFFFFFu, diff, off);
    if (tid < NCLASS && lane == 0) s_fin[wrp] = diff;
    __syncthreads();

    if (tid == 0) {
        const float extra = (s_fin[0] + s_fin[1] + s_fin[2] + s_fin[3]) / (float)n;
        out[0] = -s_fin[4] / (float)n + extra;
    }
}

extern "C" void kernel_launch(void* const* d_in, const int* in_sizes, int n_in,
                              void* d_out, int out_size) {
    const float* pred = (const float*)d_in[0];
    const int*   tgt  = (const int*)d_in[1];
    float*       out  = (float*)d_out;
    const int n = in_sizes[1];  // number of rows / targets

    loss_fused_kernel<<<NBLK, NTHR>>>(pred, tgt, out, n);
}